// round 13
// baseline (speedup 1.0000x reference)
#include <cuda_runtime.h>
#include <cuda_bf16.h>
#include <cstdint>

// ---------------------------------------------------------------------------
// FullyConnectedTensorProduct: 128x0e+128x1o+128x2e (x) 1x0e+1x1o+1x2e
//                              -> 128x0e+128x1o+128x2e, B = 32768
// Inputs: x1 [B,1152] f32, x2 [B,9] f32, ws [11,128,1,128] f32 -> out [B,1152]
//
// R12 post-mortem: tp_main L1-bound (L1=73%, fma=48.5%) because lane-uniform
// A-values were read via broadcast LDS (16 B useful / access). R13: lane=batch
// layout -> A LDS.32 with 32 distinct lanes = 128 B useful/access; ws becomes
// warp-uniform LDG.128 (1 line) whose u64 halves are already the {w,w+1} f32x2
// operands. x1 staged coalesced into smem; output transposed through smem.
// Block: 512 thr (16 warps), 32 batches (lane=b), warp = 8-w group,
// acc[4 wp][9 slot] u64 = 72 regs, 1 CTA/SM, smem 105.7 KB.
//
// c-order (35): p2:0-4, p5:5-9, p7:10-14, p10:15-19, p1:20-22, p3:23-25,
//               p6:26-28, p8:29-31, p0:32, p4:33, p9:34
// slots: 0 = l0; 1..3 = l1 k; 4..8 = l2 k.
// ---------------------------------------------------------------------------

#define NTHREADS 512
#define TB 32         // batches per block (lane = batch)
#define KC 16         // u-chunk (warp = staging u)

typedef unsigned long long u64;

// Runtime-indexed tables must be __constant__.
__constant__ int c_l1[11]   = {0,0,0,1,1,1,1,2,2,2,2};
__constant__ int c_l2[11]   = {0,1,2,0,1,1,2,0,1,2,2};
__constant__ int c_lo[11]   = {0,1,2,1,0,2,1,2,1,0,2};
__constant__ int c_goff[11] = {0,1,4,9,18,21,36,45,70,85,90};
__constant__ int c_s2off[3] = {0,1,4};

// Scaled Wigner-3j tensors: g_W3[p][i][j][k], padded 5x5x5, pre-multiplied by
// sqrt(alpha_p)/frobenius_norm.
__device__ float g_W3[11 * 125];

// ---------------------------------------------------------------------------
// Init kernel (parallel, from R12): block = path, 128 threads. ~10 us.
// ---------------------------------------------------------------------------
__device__ __forceinline__ double dfact(int n) {
    double r = 1.0;
    for (int i = 2; i <= n; i++) r *= (double)i;
    return r;
}

__global__ void tp_init_w3() {
    const int p = blockIdx.x;      // 0..10
    const int t = threadIdx.x;     // 0..127
    const int l1 = c_l1[p], l2 = c_l2[p], l3 = c_lo[p];
    const int n1 = 2 * l1 + 1, n2 = 2 * l2 + 1, n3 = 2 * l3 + 1;
    const int nTot = n1 * n2 * n3;

    __shared__ double sC[125];
    __shared__ double sQr[3][25], sQi[3][25];
    __shared__ double sCr[125];
    __shared__ double sScale;

    // --- Phase 1a: SU(2) Clebsch-Gordan, one entry per thread ---
    if (t < nTot) {
        int a = t / (n2 * n3), rem = t % (n2 * n3), b = rem / n3, c = rem % n3;
        int m1 = a - l1, m2 = b - l2, m3 = c - l3;
        double v = 0.0;
        if (m1 + m2 == m3) {
            double pref = sqrt((double)(2 * l3 + 1) * dfact(l3 + l1 - l2) * dfact(l3 - l1 + l2) *
                               dfact(l1 + l2 - l3) / dfact(l1 + l2 + l3 + 1));
            pref *= sqrt(dfact(l3 + m3) * dfact(l3 - m3) * dfact(l1 - m1) * dfact(l1 + m1) *
                         dfact(l2 - m2) * dfact(l2 + m2));
            double s = 0.0;
            for (int k = 0; k <= l1 + l2 - l3; k++) {
                if (l1 - m1 - k < 0 || l2 + m2 - k < 0 ||
                    l3 - l2 + m1 + k < 0 || l3 - l1 - m2 + k < 0) continue;
                double term = 1.0 / (dfact(k) * dfact(l1 + l2 - l3 - k) * dfact(l1 - m1 - k) *
                                     dfact(l2 + m2 - k) * dfact(l3 - l2 + m1 + k) *
                                     dfact(l3 - l1 - m2 + k));
                s += (k & 1) ? -term : term;
            }
            v = pref * s;
        }
        sC[t] = v;
    }

    // --- Phase 1b: real-basis matrices q(l) = (-i)^l * base ---
    if (t < 75) {
        int mt = t / 25, e = t % 25;
        int l = (mt == 0) ? l1 : (mt == 1) ? l2 : l3;
        int n = 2 * l + 1;
        int r = e / 5, cc = e % 5;
        double qr = 0.0, qi = 0.0;
        if (r < n && cc < n) {
            double inv = 1.0 / sqrt(2.0);
            int m = r - l;
            if (m < 0) {
                if (cc == 2 * l - r) qr = inv;
                if (cc == r)         qi = -inv;
            } else if (m == 0) {
                if (cc == l) qr = 1.0;
            } else {
                double sgn = (m & 1) ? -1.0 : 1.0;
                if (cc == r)         qr = sgn * inv;
                if (cc == 2 * l - r) qi = sgn * inv;
            }
            int ph = l & 3;
            double rr = qr, ii = qi;
            if (ph == 1)      { qr =  ii; qi = -rr; }
            else if (ph == 2) { qr = -rr; qi = -ii; }
            else if (ph == 3) { qr = -ii; qi =  rr; }
        }
        sQr[mt][e] = qr;
        sQi[mt][e] = qi;
    }
    __syncthreads();

    // --- Phase 2: Cr[j,l,m] ---
    if (t < nTot) {
        int j = t / (n2 * n3), rem = t % (n2 * n3), lc = rem / n3, m = rem % n3;
        double re = 0.0;
        for (int i = 0; i < n1; i++) {
            double q1r = sQr[0][i * 5 + j], q1i = sQi[0][i * 5 + j];
            for (int k = 0; k < n2; k++) {
                double q2r = sQr[1][k * 5 + lc], q2i = sQi[1][k * 5 + lc];
                double t1r = q1r * q2r - q1i * q2i;
                double t1i = q1r * q2i + q1i * q2r;
                for (int n = 0; n < n3; n++) {
                    double c = sC[i * (n2 * n3) + k * n3 + n];
                    if (c == 0.0) continue;
                    double q3r = sQr[2][n * 5 + m], q3i = -sQi[2][n * 5 + m];
                    re += c * (t1r * q3r - t1i * q3i);
                }
            }
        }
        sCr[t] = re;
    }
    __syncthreads();

    // --- Phase 3: Frobenius + alpha ---
    if (t == 0) {
        double f = 0.0;
        for (int e = 0; e < nTot; e++) f += sCr[e] * sCr[e];
        double alpha = (l3 == 0) ? (1.0 / 384.0) : (l3 == 1) ? (3.0 / 512.0) : (5.0 / 512.0);
        sScale = sqrt(alpha) / sqrt(f);
    }
    __syncthreads();

    if (t < 125) {
        int j = t / 25, rem = t % 25, lc = rem / 5, m = rem % 5;
        float v = 0.0f;
        if (j < n1 && lc < n2 && m < n3)
            v = (float)(sCr[j * (n2 * n3) + lc * n3 + m] * sScale);
        g_W3[p * 125 + t] = v;
    }
}

// ---------------------------------------------------------------------------
// Packed f32x2 FMA (SASS FFMA2 — only reachable via PTX).
// ---------------------------------------------------------------------------
__device__ __forceinline__ void fma2(u64& d, u64 a, u64 b) {
    asm("fma.rn.f32x2 %0, %1, %2, %0;" : "+l"(d) : "l"(a), "l"(b));
}

__device__ __forceinline__ float2 u2f(u64 v) {
    float2 r;
    r.x = __uint_as_float((unsigned)(v & 0xffffffffULL));
    r.y = __uint_as_float((unsigned)(v >> 32));
    return r;
}

// ---------------------------------------------------------------------------
// A-staging: one path; lane = batch, warp = u. Writes sA[u][c][b] (stride TB).
// ---------------------------------------------------------------------------
template <int L1V, int LOV, int GOFF, int C0>
__device__ __forceinline__ void stage_path2(const float* __restrict__ x0,
                                            const float* __restrict__ x1p,
                                            const float* __restrict__ x2p,
                                            const float* __restrict__ gb,
                                            float* __restrict__ aBase) {
    constexpr int nI = 2 * L1V + 1, nK = 2 * LOV + 1;
    const float* xs = (L1V == 0) ? x0 : (L1V == 1) ? x1p : x2p;
    float xv[nI];
#pragma unroll
    for (int i = 0; i < nI; i++) xv[i] = xs[i];
#pragma unroll
    for (int k = 0; k < nK; k++) {
        float s = 0.0f;
#pragma unroll
        for (int i = 0; i < nI; i++) s = fmaf(xv[i], gb[GOFF + i * nK + k], s);
        aBase[(C0 + k) * TB] = s;
    }
}

// ---------------------------------------------------------------------------
// Consumption: one path. ws loads are warp-uniform LDG.128 whose u64 halves
// are the packed {w,w+1} operands; A is a per-lane LDS.32 + 1 dup-mov.
// ---------------------------------------------------------------------------
template <int P, int NK, int C0, int S0>
__device__ __forceinline__ void path_consume(const float* __restrict__ wsu,
                                             const float* __restrict__ aRow,
                                             u64 (&acc)[4][9]) {
    ulonglong2 wA = *reinterpret_cast<const ulonglong2*>(wsu + P * 16384);      // w0..w3
    ulonglong2 wB = *reinterpret_cast<const ulonglong2*>(wsu + P * 16384 + 4);  // w4..w7
#pragma unroll
    for (int k = 0; k < NK; k++) {
        float a = aRow[(C0 + k) * TB];
        u64 ad;
        asm("mov.b64 %0, {%1, %1};" : "=l"(ad) : "f"(a));
        fma2(acc[0][S0 + k], ad, wA.x);
        fma2(acc[1][S0 + k], ad, wA.y);
        fma2(acc[2][S0 + k], ad, wB.x);
        fma2(acc[3][S0 + k], ad, wB.y);
    }
}

// ---------------------------------------------------------------------------
// Main kernel. 512 threads, 32 batches/block (lane=batch), warp = 8-w group.
// smem (floats): sG [32][121] @0, sX1 [32][145] @3872, sA [16][35][32] @8512
// (sA overlaid by sOut [32][289] during the output flush).
// ---------------------------------------------------------------------------
__global__ void __launch_bounds__(NTHREADS, 1)
tp_main(const float* __restrict__ x1, const float* __restrict__ x2,
        const float* __restrict__ ws, float* __restrict__ out) {
    extern __shared__ float smem[];
    float* sG  = smem;               // [32][121]  (odd stride: conflict-free)
    float* sX1 = smem + 3872;        // [32][145]
    float* sA  = smem + 8512;        // [16 u][35 c][32 b]

    const int tid = threadIdx.x;
    const int b0 = blockIdx.x * TB;

    // ---- G_p[i][k] = sum_j W3s[p][i][j][k] * x2[b][s2off[l2]+j] (once) ----
    if (tid < TB * 11) {
        int b = tid / 11, p = tid % 11;
        int l1 = c_l1[p], l2 = c_l2[p], lo = c_lo[p], goff = c_goff[p];
        int nI = 2 * l1 + 1, nJ = 2 * l2 + 1, nK = 2 * lo + 1;
        const float* w3 = g_W3 + p * 125;
        const float* x2b = x2 + (size_t)(b0 + b) * 9 + c_s2off[l2];
        float* G = sG + b * 121 + goff;
        for (int i = 0; i < nI; i++)
            for (int k = 0; k < nK; k++) {
                float s = 0.0f;
                for (int j = 0; j < nJ; j++)
                    s = fmaf(w3[i * 25 + j * 5 + k], x2b[j], s);
                G[i * nK + k] = s;
            }
    }
    __syncthreads();

    const int warp = tid >> 5;       // 0..15 : w-group (w = 8*warp .. 8*warp+7)
    const int lane = tid & 31;       // batch within block

    u64 acc[4][9];
#pragma unroll
    for (int wp = 0; wp < 4; wp++)
#pragma unroll
        for (int s = 0; s < 9; s++) acc[wp][s] = 0ULL;

    // sX1 fill mapping: 16 threads per batch row
    const int xb = tid >> 4, xj = tid & 15;
    const float* xrow = x1 + (size_t)(b0 + xb) * 1152;
    float* xdst = sX1 + xb * 145;

    const float* gb = sG + lane * 121;
    float* aBase = sA + warp * (35 * TB) + lane;   // staging: u = warp

    for (int uc = 0; uc < 128; uc += KC) {
        // ---- coalesced x1 chunk -> sX1: [0..16)=l0, [16..64)=l1, [64..144)=l2
        xdst[xj] = xrow[uc + xj];
#pragma unroll
        for (int r = 0; r < 3; r++)
            xdst[16 + xj + 16 * r] = xrow[128 + 3 * uc + xj + 16 * r];
#pragma unroll
        for (int r = 0; r < 5; r++)
            xdst[64 + xj + 16 * r] = xrow[512 + 5 * uc + xj + 16 * r];
        __syncthreads();

        // ---- stage A[u=warp][c][b=lane] ----
        {
            const float* sxb = sX1 + lane * 145;
            const float* px0 = sxb + warp;              // l0
            const float* px1 = sxb + 16 + 3 * warp;     // l1
            const float* px2 = sxb + 64 + 5 * warp;     // l2
            stage_path2<0, 2,  4,  0>(px0, px1, px2, gb, aBase);   // p2
            stage_path2<1, 2, 21,  5>(px0, px1, px2, gb, aBase);   // p5
            stage_path2<2, 2, 45, 10>(px0, px1, px2, gb, aBase);   // p7
            stage_path2<2, 2, 90, 15>(px0, px1, px2, gb, aBase);   // p10
            stage_path2<0, 1,  1, 20>(px0, px1, px2, gb, aBase);   // p1
            stage_path2<1, 1,  9, 23>(px0, px1, px2, gb, aBase);   // p3
            stage_path2<1, 1, 36, 26>(px0, px1, px2, gb, aBase);   // p6
            stage_path2<2, 1, 70, 29>(px0, px1, px2, gb, aBase);   // p8
            stage_path2<0, 0,  0, 32>(px0, px1, px2, gb, aBase);   // p0
            stage_path2<1, 0, 18, 33>(px0, px1, px2, gb, aBase);   // p4
            stage_path2<2, 0, 85, 34>(px0, px1, px2, gb, aBase);   // p9
        }
        __syncthreads();

        // ---- consume: FMA-bound hot loop ----
#pragma unroll 1
        for (int ul = 0; ul < KC; ul++) {
            const float* wsu = ws + (size_t)(uc + ul) * 128 + warp * 8;
            const float* aRow = sA + ul * (35 * TB) + lane;
            path_consume<2, 5,  0, 4>(wsu, aRow, acc);
            path_consume<5, 5,  5, 4>(wsu, aRow, acc);
            path_consume<7, 5, 10, 4>(wsu, aRow, acc);
            path_consume<10,5, 15, 4>(wsu, aRow, acc);
            path_consume<1, 3, 20, 1>(wsu, aRow, acc);
            path_consume<3, 3, 23, 1>(wsu, aRow, acc);
            path_consume<6, 3, 26, 1>(wsu, aRow, acc);
            path_consume<8, 3, 29, 1>(wsu, aRow, acc);
            path_consume<0, 1, 32, 0>(wsu, aRow, acc);
            path_consume<4, 1, 33, 0>(wsu, aRow, acc);
            path_consume<9, 1, 34, 0>(wsu, aRow, acc);
        }
        __syncthreads();
    }

    // ---- output flush: 4 sections of 288 cols through smem transpose ----
    float* sOut = sA;   // overlay: [32][289]
#pragma unroll 1
    for (int sec = 0; sec < 4; sec++) {
        const int base = sec * 288;
#pragma unroll
        for (int wp = 0; wp < 4; wp++)
#pragma unroll
            for (int s = 0; s < 9; s++) {
                float2 v = u2f(acc[wp][s]);
#pragma unroll
                for (int wi = 0; wi < 2; wi++) {
                    int w = warp * 8 + wp * 2 + wi;
                    int off = (s == 0) ? w
                             : (s < 4) ? 128 + w * 3 + (s - 1)
                                       : 512 + w * 5 + (s - 4);
                    int rel = off - base;
                    float val = wi ? v.y : v.x;
                    if (rel >= 0 && rel < 288)
                        sOut[lane * 289 + rel] = val;
                }
            }
        __syncthreads();
        for (int i = tid; i < TB * 288; i += NTHREADS) {
            int bb = i / 288;
            int off = i - bb * 288;
            out[(size_t)(b0 + bb) * 1152 + base + off] = sOut[bb * 289 + off];
        }
        __syncthreads();
    }
}

// ---------------------------------------------------------------------------
extern "C" void kernel_launch(void* const* d_in, const int* in_sizes, int n_in,
                              void* d_out, int out_size) {
    const float* x1 = (const float*)d_in[0];
    const float* x2 = (const float*)d_in[1];
    const float* ws = (const float*)d_in[2];
    float* out = (float*)d_out;

    int B = in_sizes[0] / 1152;              // 32768
    int grid = B / TB;                       // 1024

    // floats: sG 32*121=3872, sX1 32*145=4640, sA max(16*35*32, 32*289)=17920
    const int smem_bytes = (3872 + 4640 + 17920) * 4;   // 105,728 B
    cudaFuncSetAttribute(tp_main, cudaFuncAttributeMaxDynamicSharedMemorySize, smem_bytes);

    tp_init_w3<<<11, 128>>>();
    tp_main<<<grid, NTHREADS, smem_bytes>>>(x1, x2, ws, out);
}